// round 6
// baseline (speedup 1.0000x reference)
#include <cuda_runtime.h>

// Problem constants (LinearDiffusion_2860448219950)
#define NN   8192
#define HH   4
#define EE   131072
#define DD   64
#define TBL  (1 << 19)
#define TBLM (TBL - 1)

// ---------------- device scratch (no allocations allowed) ----------------
// Packed hash entry: high32 = key+1 (nonzero), low32 = prio. Empty slot = 0.
__device__ unsigned long long g_tbl[TBL];     // 4 MB
__device__ int          g_slot[2 * EE];       // slot each entry landed in
__device__ int          g_deg[NN];
__device__ int          g_rowstart[NN + 1];
__device__ int          g_rowfill[NN];
__device__ float        g_rowsum[NN * HH];    // 16B-aligned, read as float4
__device__ int          g_nnz;
__device__ int          g_tmp_i[2 * EE];
__device__ int          g_tmp_j[2 * EE];
__device__ float4       g_evals[2 * EE];      // unnormalized e-quad per winner
__device__ int          g_cols[2 * EE];
__device__ float4       g_vals[2 * EE];       // per-head normalized values
__device__ float        g_x[2][NN * DD];      // ping-pong SpMM buffers

__device__ __forceinline__ unsigned int hash_key(unsigned int key) {
    return (key * 2654435761u) >> 13;  // 19-bit hash
}

// Insert (i,j) with priority prio; returns final slot. Keeps max prio per key.
// Slot value transitions are monotone: 0 -> (key,p) -> (key,p'>p); no ABA.
__device__ __forceinline__ int ht_insert(unsigned int key, unsigned int prio) {
    unsigned long long desired = ((unsigned long long)(key + 1u) << 32) | prio;
    unsigned int s = hash_key(key) & TBLM;
    while (true) {
        unsigned long long cur = g_tbl[s];
        if (cur == 0ULL) {
            unsigned long long old = atomicCAS(&g_tbl[s], 0ULL, desired);
            if (old == 0ULL) return (int)s;
            cur = old;
        }
        if ((unsigned int)(cur >> 32) == key + 1u) {
            while ((unsigned int)cur < prio) {
                unsigned long long old = atomicCAS(&g_tbl[s], cur, desired);
                if (old == cur) break;
                cur = old;
            }
            return (int)s;
        }
        s = (s + 1) & TBLM;
    }
}

// ---------------- 0: zero scratch ----------------
__global__ void k_zero() {
    int t = blockIdx.x * blockDim.x + threadIdx.x;
    int stride = gridDim.x * blockDim.x;
    for (int s = t; s < TBL; s += stride) g_tbl[s] = 0ULL;
    for (int s = t; s < NN;  s += stride) { g_deg[s] = 0; g_rowfill[s] = 0; }
    for (int s = t; s < NN * HH; s += stride) g_rowsum[s] = 0.f;
    if (t == 0) g_nnz = 0;
}

// ---------------- 1: hash insert, both passes per thread ----------------
// Pass 0 entry (src[k],dst[k]) prio=k+1; pass 1 entry (dst[k],src[k]) prio=(1<<17)+k+1.
// Last-write-wins == max prio per (i,j) key.
__global__ void k_insert(const int* __restrict__ src, const int* __restrict__ dst) {
    int k = blockIdx.x * blockDim.x + threadIdx.x;
    if (k >= EE) return;
    int i = src[k], j = dst[k];
    unsigned int key0 = ((unsigned int)i << 13) | (unsigned int)j;
    unsigned int key1 = ((unsigned int)j << 13) | (unsigned int)i;
    g_slot[k]      = ht_insert(key0, (unsigned int)k + 1u);
    g_slot[k + EE] = ht_insert(key1, (1u << 17) + (unsigned int)k + 1u);
}

// ---------------- 2: winners -> COO + degree + rowsum (direct slot lookup) ----------------
__global__ void k_winner(const int* __restrict__ src, const int* __restrict__ dst,
                         const float* __restrict__ e) {
    int k = blockIdx.x * blockDim.x + threadIdx.x;
    if (k >= EE) return;
    int i = src[k], j = dst[k];
    unsigned int prio0 = (unsigned int)k + 1u;
    unsigned int prio1 = (1u << 17) + (unsigned int)k + 1u;
    unsigned long long e0 = g_tbl[g_slot[k]];
    unsigned long long e1 = g_tbl[g_slot[k + EE]];
    bool w0 = ((unsigned int)e0 == prio0);
    bool w1 = ((unsigned int)e1 == prio1);
    if (!(w0 || w1)) return;
    float4 ev;
    ev.x = e[0 * EE + k]; ev.y = e[1 * EE + k];
    ev.z = e[2 * EE + k]; ev.w = e[3 * EE + k];
    if (w0) {
        int idx = atomicAdd(&g_nnz, 1);
        g_tmp_i[idx] = i; g_tmp_j[idx] = j; g_evals[idx] = ev;
        atomicAdd(&g_deg[i], 1);
        atomicAdd(&g_rowsum[i * HH + 0], ev.x);
        atomicAdd(&g_rowsum[i * HH + 1], ev.y);
        atomicAdd(&g_rowsum[i * HH + 2], ev.z);
        atomicAdd(&g_rowsum[i * HH + 3], ev.w);
    }
    if (w1) {
        int idx = atomicAdd(&g_nnz, 1);
        g_tmp_i[idx] = j; g_tmp_j[idx] = i; g_evals[idx] = ev;
        atomicAdd(&g_deg[j], 1);
        atomicAdd(&g_rowsum[j * HH + 0], ev.x);
        atomicAdd(&g_rowsum[j * HH + 1], ev.y);
        atomicAdd(&g_rowsum[j * HH + 2], ev.z);
        atomicAdd(&g_rowsum[j * HH + 3], ev.w);
    }
}

// ---------------- 3: exclusive scan of degrees (shuffle-based) ----------------
__global__ void k_scan() {
    __shared__ int warpsum[32];
    int tid = threadIdx.x;      // 1024 threads, 8 rows each
    int lane = tid & 31, warp = tid >> 5;
    int4 a = ((const int4*)g_deg)[tid * 2];
    int4 b = ((const int4*)g_deg)[tid * 2 + 1];
    int l0 = 0, l1 = a.x, l2 = l1 + a.y, l3 = l2 + a.z, l4 = l3 + a.w;
    int l5 = l4 + b.x, l6 = l5 + b.y, l7 = l6 + b.z;
    int tot = l7 + b.w;
    int run = tot;
#pragma unroll
    for (int off = 1; off < 32; off <<= 1) {
        int v = __shfl_up_sync(0xFFFFFFFFu, run, off);
        if (lane >= off) run += v;
    }
    if (lane == 31) warpsum[warp] = run;
    __syncthreads();
    if (warp == 0) {
        int w = warpsum[lane];
#pragma unroll
        for (int off = 1; off < 32; off <<= 1) {
            int v = __shfl_up_sync(0xFFFFFFFFu, w, off);
            if (lane >= off) w += v;
        }
        warpsum[lane] = w;
    }
    __syncthreads();
    int excl = run - tot + (warp > 0 ? warpsum[warp - 1] : 0);
    int4 r0 = make_int4(excl + l0, excl + l1, excl + l2, excl + l3);
    int4 r1 = make_int4(excl + l4, excl + l5, excl + l6, excl + l7);
    ((int4*)g_rowstart)[tid * 2] = r0;
    ((int4*)g_rowstart)[tid * 2 + 1] = r1;
    if (tid == 1023) g_rowstart[NN] = excl + tot;
}

// ---------------- 4: CSR fill with normalized per-head values ----------------
__global__ void k_fill() {
    int t = blockIdx.x * blockDim.x + threadIdx.x;
    if (t >= g_nnz) return;
    int i = g_tmp_i[t];
    int pos = g_rowstart[i] + atomicAdd(&g_rowfill[i], 1);
    g_cols[pos] = g_tmp_j[t];
    float4 ev = g_evals[t];
    float4 rs = ((const float4*)g_rowsum)[i];
    float4 v;
    v.x = ev.x / rs.x; v.y = ev.y / rs.y; v.z = ev.z / rs.z; v.w = ev.w / rs.w;
    g_vals[pos] = v;
}

// ---------------- 5: SpMM  xout = A_norm @ xin ; res (+)= xout * invf ----------------
// (H, N, 16)-flat layout == flat h/out (reference uses raw reshape).
// 64 threads per row: head = (c>>4), dim d = c&15. 4-deep unrolled gather pipeline.
template <bool FIRST>
__global__ void k_spmm(const float* __restrict__ xin, float* __restrict__ xout,
                       float* __restrict__ res, float invf) {
    int row = blockIdx.x * 2 + (threadIdx.x >> 6);
    int c = threadIdx.x & 63;
    int head = c >> 4;
    int d = c & 15;
    int hbase = head << 17;   // head * N * 16
    int s = g_rowstart[row];
    int epos = g_rowstart[row + 1];
    const float* vals = (const float*)g_vals;
    float acc = 0.f;
    int t = s;
#pragma unroll 1
    for (; t + 4 <= epos; t += 4) {
        int j0 = g_cols[t], j1 = g_cols[t + 1], j2 = g_cols[t + 2], j3 = g_cols[t + 3];
        float v0 = vals[(t) * 4 + head];
        float v1 = vals[(t + 1) * 4 + head];
        float v2 = vals[(t + 2) * 4 + head];
        float v3 = vals[(t + 3) * 4 + head];
        float x0 = __ldg(&xin[hbase + (j0 << 4) + d]);
        float x1 = __ldg(&xin[hbase + (j1 << 4) + d]);
        float x2 = __ldg(&xin[hbase + (j2 << 4) + d]);
        float x3 = __ldg(&xin[hbase + (j3 << 4) + d]);
        acc += v0 * x0 + v1 * x1 + v2 * x2 + v3 * x3;
    }
    for (; t < epos; t++) {
        int j = g_cols[t];
        acc += vals[t * 4 + head] * __ldg(&xin[hbase + (j << 4) + d]);
    }
    int o = hbase + (row << 4) + d;
    xout[o] = acc;
    if (FIRST)
        res[o] = __ldg(&xin[o]) + acc;   // result = h + x1/1!
    else
        res[o] += acc * invf;
}

// ---------------- launch ----------------
extern "C" void kernel_launch(void* const* d_in, const int* in_sizes, int n_in,
                              void* d_out, int out_size) {
    const float* h   = (const float*)d_in[0];
    const float* e   = (const float*)d_in[1];
    const int*   src = (const int*)d_in[2];
    const int*   dst = (const int*)d_in[3];
    float* out = (float*)d_out;

    k_zero<<<512, 256>>>();
    k_insert<<<(EE + 255) / 256, 256>>>(src, dst);
    k_winner<<<(EE + 255) / 256, 256>>>(src, dst, e);
    k_scan<<<1, 1024>>>();
    k_fill<<<(2 * EE + 255) / 256, 256>>>();

    float* xa;  float* xb;
    cudaGetSymbolAddress((void**)&xa, g_x);
    xb = xa + NN * DD;

    const float invf[6] = {1.0f, 0.5f, 1.0f / 6.0f, 1.0f / 24.0f, 1.0f / 120.0f, 1.0f / 720.0f};
    // SpMM 0: h -> xa (fused result = h + x1)
    k_spmm<true><<<NN / 2, 128>>>(h, xa, out, invf[0]);
    const float* cur = xa;
    // Correct ping-pong: it=1 -> xb, it=2 -> xa, it=3 -> xb, ...
    float* bufs[2] = {xa, xb};
    for (int it = 1; it < 6; it++) {
        float* nxt = bufs[it & 1];
        k_spmm<false><<<NN / 2, 128>>>(cur, nxt, out, invf[it]);
        cur = nxt;
    }
}

// round 7
// speedup vs baseline: 1.2388x; 1.2388x over previous
#include <cuda_runtime.h>

// Problem constants (LinearDiffusion_2860448219950)
#define NN   8192
#define HH   4
#define EE   131072
#define DD   64
#define WW   96                 // ELL width (max degree ~58 for Poisson(32) over 8192 rows)
#define TBL  (1 << 19)
#define TBLM (TBL - 1)

// ---------------- device scratch (no allocations allowed) ----------------
// Packed hash entry: high32 = key+1 (nonzero), low32 = prio. Empty slot = 0.
__device__ unsigned long long g_tbl[TBL];       // 4 MB
__device__ int          g_slot[2 * EE];         // slot each entry landed in
__device__ int          g_deg[NN];
__device__ float        g_rowsum[NN * HH];      // per-(row,head) sum of winner e
__device__ int          g_cols[NN * WW];        // ELL columns
__device__ float4       g_evals[NN * WW];       // ELL unnormalized e-quads
__device__ float        g_x[2][NN * DD];        // ping-pong SpMM buffers

__device__ __forceinline__ unsigned int hash_key(unsigned int key) {
    return (key * 2654435761u) >> 13;  // 19-bit hash
}

// Insert key with priority prio; returns final slot. Keeps max prio per key.
// Slot transitions are monotone (0 -> (key,p) -> (key,p'>p)); no ABA.
__device__ __forceinline__ int ht_insert(unsigned int key, unsigned int prio) {
    unsigned long long desired = ((unsigned long long)(key + 1u) << 32) | prio;
    unsigned int s = hash_key(key) & TBLM;
    while (true) {
        unsigned long long cur = g_tbl[s];
        if (cur == 0ULL) {
            unsigned long long old = atomicCAS(&g_tbl[s], 0ULL, desired);
            if (old == 0ULL) return (int)s;
            cur = old;
        }
        if ((unsigned int)(cur >> 32) == key + 1u) {
            while ((unsigned int)cur < prio) {
                unsigned long long old = atomicCAS(&g_tbl[s], cur, desired);
                if (old == cur) break;
                cur = old;
            }
            return (int)s;
        }
        s = (s + 1) & TBLM;
    }
}

// ---------------- 0: zero scratch ----------------
__global__ void k_zero() {
    int t = blockIdx.x * blockDim.x + threadIdx.x;
    int stride = gridDim.x * blockDim.x;
    for (int s = t; s < TBL; s += stride) g_tbl[s] = 0ULL;
    for (int s = t; s < NN;  s += stride) g_deg[s] = 0;
    for (int s = t; s < NN * HH; s += stride) g_rowsum[s] = 0.f;
}

// ---------------- 1: hash insert, one entry per thread (full parallelism) ----------------
// t < EE: pass-0 entry (src[k],dst[k]) prio=k+1.
// t >= EE: pass-1 entry (dst[k],src[k]) prio=(1<<17)+k+1 (applied after => higher prio).
__global__ void k_insert(const int* __restrict__ src, const int* __restrict__ dst) {
    int t = blockIdx.x * blockDim.x + threadIdx.x;
    if (t >= 2 * EE) return;
    int pass = (t >= EE);
    int k = t - (pass ? EE : 0);
    int a = src[k], b = dst[k];
    int i = pass ? b : a;
    int j = pass ? a : b;
    unsigned int key  = ((unsigned int)i << 13) | (unsigned int)j;
    unsigned int prio = (((unsigned int)pass << 17)) + (unsigned int)k + 1u;
    g_slot[t] = ht_insert(key, prio);
}

// ---------------- 2: winners -> ELL + degree + rowsum ----------------
__global__ void k_winner(const int* __restrict__ src, const int* __restrict__ dst,
                         const float* __restrict__ e) {
    int t = blockIdx.x * blockDim.x + threadIdx.x;
    if (t >= 2 * EE) return;
    int pass = (t >= EE);
    int k = t - (pass ? EE : 0);
    unsigned int prio = (((unsigned int)pass << 17)) + (unsigned int)k + 1u;
    unsigned long long entry = g_tbl[g_slot[t]];
    if ((unsigned int)entry != prio) return;   // not the last write for this (i,j)
    int a = src[k], b = dst[k];
    int i = pass ? b : a;
    int j = pass ? a : b;
    float4 ev;
    ev.x = e[0 * EE + k]; ev.y = e[1 * EE + k];
    ev.z = e[2 * EE + k]; ev.w = e[3 * EE + k];
    int pos = atomicAdd(&g_deg[i], 1);
    if (pos < WW) {
        g_cols[i * WW + pos]  = j;
        g_evals[i * WW + pos] = ev;
    }
    atomicAdd(&g_rowsum[i * HH + 0], ev.x);
    atomicAdd(&g_rowsum[i * HH + 1], ev.y);
    atomicAdd(&g_rowsum[i * HH + 2], ev.z);
    atomicAdd(&g_rowsum[i * HH + 3], ev.w);
}

// ---------------- 3: SpMM  xi = (A_unnorm @ xin) / rowsum ; res (+)= xi * invf ----------------
// (H, N, 16)-flat state layout == flat h/out (reference uses raw reshape).
// 16 threads per row: head = (c>>2), quad q = c&3 covers dims 4q..4q+3 (float4).
// Normalization applied once per (row, head) at the end.
template <bool FIRST>
__global__ void k_spmm(const float4* __restrict__ xin4, float4* __restrict__ xout4,
                       float4* __restrict__ res4, float invf) {
    int tid = threadIdx.x;
    int row = blockIdx.x * 16 + (tid >> 4);
    int c = tid & 15;
    int head = c >> 2;
    int q = c & 3;
    int hb4 = head << 15;                 // head * N * 16 / 4
    int deg = g_deg[row];
    float rinv = 1.0f / g_rowsum[row * HH + head];
    const float* vals = (const float*)g_evals;
    int base = row * WW;
    float4 acc = make_float4(0.f, 0.f, 0.f, 0.f);
    int r = 0;
#pragma unroll 1
    for (; r + 4 <= deg; r += 4) {
        int j0 = g_cols[base + r];
        int j1 = g_cols[base + r + 1];
        int j2 = g_cols[base + r + 2];
        int j3 = g_cols[base + r + 3];
        float v0 = vals[(base + r) * 4 + head];
        float v1 = vals[(base + r + 1) * 4 + head];
        float v2 = vals[(base + r + 2) * 4 + head];
        float v3 = vals[(base + r + 3) * 4 + head];
        float4 x0 = __ldg(&xin4[hb4 + (j0 << 2) + q]);
        float4 x1 = __ldg(&xin4[hb4 + (j1 << 2) + q]);
        float4 x2 = __ldg(&xin4[hb4 + (j2 << 2) + q]);
        float4 x3 = __ldg(&xin4[hb4 + (j3 << 2) + q]);
        acc.x += v0 * x0.x + v1 * x1.x + v2 * x2.x + v3 * x3.x;
        acc.y += v0 * x0.y + v1 * x1.y + v2 * x2.y + v3 * x3.y;
        acc.z += v0 * x0.z + v1 * x1.z + v2 * x2.z + v3 * x3.z;
        acc.w += v0 * x0.w + v1 * x1.w + v2 * x2.w + v3 * x3.w;
    }
    for (; r < deg; r++) {
        int j = g_cols[base + r];
        float v = vals[(base + r) * 4 + head];
        float4 x = __ldg(&xin4[hb4 + (j << 2) + q]);
        acc.x += v * x.x; acc.y += v * x.y; acc.z += v * x.z; acc.w += v * x.w;
    }
    float4 xi = make_float4(acc.x * rinv, acc.y * rinv, acc.z * rinv, acc.w * rinv);
    int o = hb4 + (row << 2) + q;
    xout4[o] = xi;
    if (FIRST) {
        float4 hv = __ldg(&xin4[o]);      // xin is h on the first hop
        res4[o] = make_float4(hv.x + xi.x, hv.y + xi.y, hv.z + xi.z, hv.w + xi.w);
    } else {
        float4 rv = res4[o];
        res4[o] = make_float4(rv.x + xi.x * invf, rv.y + xi.y * invf,
                              rv.z + xi.z * invf, rv.w + xi.w * invf);
    }
}

// ---------------- launch ----------------
extern "C" void kernel_launch(void* const* d_in, const int* in_sizes, int n_in,
                              void* d_out, int out_size) {
    const float* h   = (const float*)d_in[0];
    const float* e   = (const float*)d_in[1];
    const int*   src = (const int*)d_in[2];
    const int*   dst = (const int*)d_in[3];
    float4* out4 = (float4*)d_out;

    k_zero<<<1024, 256>>>();
    k_insert<<<(2 * EE + 255) / 256, 256>>>(src, dst);
    k_winner<<<(2 * EE + 255) / 256, 256>>>(src, dst, e);

    float* xa;  float* xb;
    cudaGetSymbolAddress((void**)&xa, g_x);
    xb = xa + NN * DD;

    const float invf[6] = {1.0f, 0.5f, 1.0f / 6.0f, 1.0f / 24.0f, 1.0f / 120.0f, 1.0f / 720.0f};
    // Hop 1: h -> xa, fused res = h + x1
    k_spmm<true><<<NN / 16, 256>>>((const float4*)h, (float4*)xa, out4, invf[0]);
    const float* cur = xa;
    float* bufs[2] = {xa, xb};            // it=1 -> xb, it=2 -> xa, alternating vs cur
    for (int it = 1; it < 6; it++) {
        float* nxt = bufs[it & 1];
        k_spmm<false><<<NN / 16, 256>>>((const float4*)cur, (float4*)nxt, out4, invf[it]);
        cur = nxt;
    }
}

// round 8
// speedup vs baseline: 1.4241x; 1.1496x over previous
#include <cuda_runtime.h>

// Problem constants (LinearDiffusion_2860448219950)
#define NN   8192
#define HH   4
#define EE   131072
#define DD   64
#define WW   96                 // ELL width (max degree ~58 for Poisson(32) over 8192 rows)
#define TBL  (1 << 19)
#define TBLM (TBL - 1)

// ---------------- device scratch (no allocations allowed) ----------------
// Packed hash entry: high32 = key+1 (nonzero), low32 = prio. Empty slot = 0.
__device__ unsigned long long g_tbl[TBL];       // 4 MB
__device__ int          g_slot[2 * EE];         // slot each entry landed in
__device__ int          g_deg[NN];
__device__ float        g_rowsum[NN * HH];      // per-(row,head) sum of winner e
__device__ int          g_cols[NN * WW];        // ELL columns
__device__ float4       g_evals[NN * WW];       // ELL unnormalized e-quads
__device__ float        g_x[2][NN * DD];        // ping-pong SpMM buffers

__device__ __forceinline__ unsigned int hash_key(unsigned int key) {
    return (key * 2654435761u) >> 13;  // 19-bit hash
}

// Insert key with priority prio; returns final slot. Keeps max prio per key.
// Slot transitions are monotone (0 -> (key,p) -> (key,p'>p)); no ABA.
__device__ __forceinline__ int ht_insert(unsigned int key, unsigned int prio) {
    unsigned long long desired = ((unsigned long long)(key + 1u) << 32) | prio;
    unsigned int s = hash_key(key) & TBLM;
    while (true) {
        unsigned long long cur = g_tbl[s];
        if (cur == 0ULL) {
            unsigned long long old = atomicCAS(&g_tbl[s], 0ULL, desired);
            if (old == 0ULL) return (int)s;
            cur = old;
        }
        if ((unsigned int)(cur >> 32) == key + 1u) {
            while ((unsigned int)cur < prio) {
                unsigned long long old = atomicCAS(&g_tbl[s], cur, desired);
                if (old == cur) break;
                cur = old;
            }
            return (int)s;
        }
        s = (s + 1) & TBLM;
    }
}

// ---------------- 0: zero scratch ----------------
__global__ void k_zero() {
    int t = blockIdx.x * blockDim.x + threadIdx.x;
    int stride = gridDim.x * blockDim.x;
    for (int s = t; s < TBL; s += stride) g_tbl[s] = 0ULL;
    for (int s = t; s < NN;  s += stride) g_deg[s] = 0;
    for (int s = t; s < NN * HH; s += stride) g_rowsum[s] = 0.f;
}

// ---------------- 1: hash insert, one entry per thread ----------------
// t < EE: pass-0 entry (src[k],dst[k]) prio=k+1.
// t >= EE: pass-1 entry (dst[k],src[k]) prio=(1<<17)+k+1 (applied after => higher prio).
__global__ void k_insert(const int* __restrict__ src, const int* __restrict__ dst) {
    int t = blockIdx.x * blockDim.x + threadIdx.x;
    if (t >= 2 * EE) return;
    int pass = (t >= EE);
    int k = t - (pass ? EE : 0);
    int a = src[k], b = dst[k];
    int i = pass ? b : a;
    int j = pass ? a : b;
    unsigned int key  = ((unsigned int)i << 13) | (unsigned int)j;
    unsigned int prio = (((unsigned int)pass << 17)) + (unsigned int)k + 1u;
    g_slot[t] = ht_insert(key, prio);
}

// ---------------- 2: winners -> ELL + degree + rowsum ----------------
__global__ void k_winner(const int* __restrict__ src, const int* __restrict__ dst,
                         const float* __restrict__ e) {
    int t = blockIdx.x * blockDim.x + threadIdx.x;
    if (t >= 2 * EE) return;
    int pass = (t >= EE);
    int k = t - (pass ? EE : 0);
    unsigned int prio = (((unsigned int)pass << 17)) + (unsigned int)k + 1u;
    unsigned long long entry = g_tbl[g_slot[t]];
    if ((unsigned int)entry != prio) return;   // not the last write for this (i,j)
    int a = src[k], b = dst[k];
    int i = pass ? b : a;
    int j = pass ? a : b;
    float4 ev;
    ev.x = e[0 * EE + k]; ev.y = e[1 * EE + k];
    ev.z = e[2 * EE + k]; ev.w = e[3 * EE + k];
    int pos = atomicAdd(&g_deg[i], 1);
    if (pos < WW) {
        g_cols[i * WW + pos]  = j;
        g_evals[i * WW + pos] = ev;
    }
    atomicAdd(&g_rowsum[i * HH + 0], ev.x);
    atomicAdd(&g_rowsum[i * HH + 1], ev.y);
    atomicAdd(&g_rowsum[i * HH + 2], ev.z);
    atomicAdd(&g_rowsum[i * HH + 3], ev.w);
}

// ---------------- 3: SpMM  xi = (A_unnorm @ xin) / rowsum ; res (+)= xi * invf ----------------
// (H, N, 16)-flat state layout == flat h/out (reference uses raw reshape).
// 32 threads per row: lane = 16*sub + c; sub in {0,1} processes one contiguous
// half of the row's edges; c: head = c>>2, quad q = c&3 (float4 of x).
// Halves combined with shfl_xor(16); lanes 0-15 write.
template <bool FIRST>
__global__ void k_spmm(const float4* __restrict__ xin4, float4* __restrict__ xout4,
                       float4* __restrict__ res4, float invf) {
    int tid = threadIdx.x;
    int row = blockIdx.x * 8 + (tid >> 5);
    int lane = tid & 31;
    int sub = lane >> 4;
    int c = lane & 15;
    int head = c >> 2;
    int q = c & 3;
    int hb4 = head << 15;                 // head * N * 16 / 4
    int deg = g_deg[row];
    int half = (deg + 1) >> 1;
    int rbeg = sub * half;
    int rend = sub ? deg : half;
    const float* vals = (const float*)g_evals;
    int base = row * WW;
    float4 acc = make_float4(0.f, 0.f, 0.f, 0.f);
    int r = rbeg;
#pragma unroll 1
    for (; r + 4 <= rend; r += 4) {
        int j0 = g_cols[base + r];
        int j1 = g_cols[base + r + 1];
        int j2 = g_cols[base + r + 2];
        int j3 = g_cols[base + r + 3];
        float v0 = vals[(base + r) * 4 + head];
        float v1 = vals[(base + r + 1) * 4 + head];
        float v2 = vals[(base + r + 2) * 4 + head];
        float v3 = vals[(base + r + 3) * 4 + head];
        float4 x0 = __ldg(&xin4[hb4 + (j0 << 2) + q]);
        float4 x1 = __ldg(&xin4[hb4 + (j1 << 2) + q]);
        float4 x2 = __ldg(&xin4[hb4 + (j2 << 2) + q]);
        float4 x3 = __ldg(&xin4[hb4 + (j3 << 2) + q]);
        acc.x += v0 * x0.x + v1 * x1.x + v2 * x2.x + v3 * x3.x;
        acc.y += v0 * x0.y + v1 * x1.y + v2 * x2.y + v3 * x3.y;
        acc.z += v0 * x0.z + v1 * x1.z + v2 * x2.z + v3 * x3.z;
        acc.w += v0 * x0.w + v1 * x1.w + v2 * x2.w + v3 * x3.w;
    }
    for (; r < rend; r++) {
        int j = g_cols[base + r];
        float v = vals[(base + r) * 4 + head];
        float4 x = __ldg(&xin4[hb4 + (j << 2) + q]);
        acc.x += v * x.x; acc.y += v * x.y; acc.z += v * x.z; acc.w += v * x.w;
    }
    // combine the two edge-halves (lane <-> lane^16)
    acc.x += __shfl_xor_sync(0xFFFFFFFFu, acc.x, 16);
    acc.y += __shfl_xor_sync(0xFFFFFFFFu, acc.y, 16);
    acc.z += __shfl_xor_sync(0xFFFFFFFFu, acc.z, 16);
    acc.w += __shfl_xor_sync(0xFFFFFFFFu, acc.w, 16);
    if (sub == 0) {
        float rinv = 1.0f / g_rowsum[row * HH + head];
        float4 xi = make_float4(acc.x * rinv, acc.y * rinv, acc.z * rinv, acc.w * rinv);
        int o = hb4 + (row << 2) + q;
        xout4[o] = xi;
        if (FIRST) {
            float4 hv = __ldg(&xin4[o]);  // xin is h on the first hop
            res4[o] = make_float4(hv.x + xi.x, hv.y + xi.y, hv.z + xi.z, hv.w + xi.w);
        } else {
            float4 rv = res4[o];
            res4[o] = make_float4(rv.x + xi.x * invf, rv.y + xi.y * invf,
                                  rv.z + xi.z * invf, rv.w + xi.w * invf);
        }
    }
}

// ---------------- launch ----------------
extern "C" void kernel_launch(void* const* d_in, const int* in_sizes, int n_in,
                              void* d_out, int out_size) {
    const float* h   = (const float*)d_in[0];
    const float* e   = (const float*)d_in[1];
    const int*   src = (const int*)d_in[2];
    const int*   dst = (const int*)d_in[3];
    float4* out4 = (float4*)d_out;

    k_zero<<<1024, 256>>>();
    k_insert<<<(2 * EE + 255) / 256, 256>>>(src, dst);
    k_winner<<<(2 * EE + 255) / 256, 256>>>(src, dst, e);

    float* xa;  float* xb;
    cudaGetSymbolAddress((void**)&xa, g_x);
    xb = xa + NN * DD;

    const float invf[6] = {1.0f, 0.5f, 1.0f / 6.0f, 1.0f / 24.0f, 1.0f / 120.0f, 1.0f / 720.0f};
    // Hop 1: h -> xa, fused res = h + x1
    k_spmm<true><<<NN / 8, 256>>>((const float4*)h, (float4*)xa, out4, invf[0]);
    const float* cur = xa;
    float* bufs[2] = {xa, xb};            // it=1 -> xb, it=2 -> xa, alternating vs cur
    for (int it = 1; it < 6; it++) {
        float* nxt = bufs[it & 1];
        k_spmm<false><<<NN / 8, 256>>>((const float4*)cur, (float4*)nxt, out4, invf[it]);
        cur = nxt;
    }
}